// round 3
// baseline (speedup 1.0000x reference)
#include <cuda_runtime.h>
#include <cstdint>

#define MAX_NODES 50000
#define MAX_EDGES 800000

__device__ float g_agg[MAX_NODES * 64];
__device__ float g_deg[MAX_NODES];

// ---------------- packed fp32x2 helpers ----------------
__device__ __forceinline__ unsigned long long splat2(float v) {
    unsigned long long r;
    asm("mov.b64 %0, {%1, %1};" : "=l"(r) : "f"(v));
    return r;
}
__device__ __forceinline__ float2 unpack2(unsigned long long v) {
    float lo, hi;
    asm("mov.b64 {%0, %1}, %2;" : "=f"(lo), "=f"(hi) : "l"(v));
    return make_float2(lo, hi);
}
__device__ __forceinline__ unsigned long long fma2(unsigned long long a,
                                                   unsigned long long b,
                                                   unsigned long long c) {
    unsigned long long d;
    asm("fma.rn.f32x2 %0, %1, %2, %3;" : "=l"(d) : "l"(a), "l"(b), "l"(c));
    return d;
}

// ---------------------------------------------------------------------------
// Kernel 0: zero scratch
// ---------------------------------------------------------------------------
__global__ void zero_kernel(int n_nodes) {
    int i = blockIdx.x * blockDim.x + threadIdx.x;
    int stride = gridDim.x * blockDim.x;
    int tot = n_nodes * 64;
    for (int k = i; k < tot; k += stride) g_agg[k] = 0.0f;
    for (int k = i; k < n_nodes; k += stride) g_deg[k] = 0.0f;
}

// ---------------------------------------------------------------------------
// Kernel 1: edge MLP + atomic aggregation (8 edges per warp, f32x2 packed)
//
// Smem (floats), 128 threads (4 warps) per block:
//   sW1  float2[192][32]   off 0       (12288 f)  (W1e[k][l], W1e[k][l+32])
//   sW2  float2[64][32]    off 12288   (4096 f)
//   sb1  float2[32]        off 16384   (64 f)
//   sb2  float2[32]        off 16448   (64 f)
//   xw   ull2 [4w][4p][96] off 16512   (6144 f)   pair-interleaved x
//   hw   ull2 [4w][4p][32] off 22656   (2048 f)   pair-interleaved hidden
//   total 24704 f = 98816 B  -> 2 blocks/SM
// ---------------------------------------------------------------------------
#define EDGE_SMEM_FLOATS 24704

__global__ void __launch_bounds__(128, 2) edge_kernel(
    const float* __restrict__ feats,
    const int* __restrict__ edge_index,
    const float* __restrict__ edge_attr,
    const float* __restrict__ W1e, const float* __restrict__ b1e,
    const float* __restrict__ W2e, const float* __restrict__ b2e,
    float* __restrict__ e_out,
    int n_edges)
{
    extern __shared__ float smem[];
    float2* sW1 = (float2*)smem;                 // [192*32]
    float2* sW2 = (float2*)(smem + 12288);       // [64*32]
    float2* sb1 = (float2*)(smem + 16384);
    float2* sb2 = (float2*)(smem + 16448);

    int tid = threadIdx.x;
    for (int i = tid; i < 192 * 32; i += 128) {
        int k = i >> 5, l = i & 31;
        sW1[i] = make_float2(W1e[k * 64 + l], W1e[k * 64 + l + 32]);
    }
    for (int i = tid; i < 64 * 32; i += 128) {
        int k = i >> 5, l = i & 31;
        sW2[i] = make_float2(W2e[k * 64 + l], W2e[k * 64 + l + 32]);
    }
    if (tid < 32) {
        sb1[tid] = make_float2(b1e[tid], b1e[tid + 32]);
        sb2[tid] = make_float2(b2e[tid], b2e[tid + 32]);
    }
    __syncthreads();

    int warp = tid >> 5, lane = tid & 31;
    ulonglong2* xw = (ulonglong2*)(smem + 16512) + warp * 4 * 96;  // [p][kk]
    ulonglong2* hw = (ulonglong2*)(smem + 22656) + warp * 4 * 32;  // [p][kk]

    int nGroups = (n_edges + 7) >> 3;
    int gwarp = blockIdx.x * 4 + warp;
    int wstride = gridDim.x * 4;

    for (int g = gwarp; g < nGroups; g += wstride) {
        int ebase = g * 8;
        int nE = min(8, n_edges - ebase);

        int r = 0, c = 0;
        if (lane < 8) {
            int eid = ebase + min(lane, nE - 1);
            int2 rc = ((const int2*)edge_index)[eid];
            r = rc.x; c = rc.y;
        }

        // Gather: 8 edges * 48 float4 = 384 float4; write pair-interleaved
        for (int i = lane; i < 384; i += 32) {
            int j = i / 48;
            int part = (i % 48) >> 4;
            int q = i & 15;
            int rj = __shfl_sync(0xffffffffu, r, j);
            int cj = __shfl_sync(0xffffffffu, c, j);
            int eid = ebase + min(j, nE - 1);
            const float4* src;
            if (part == 0)      src = (const float4*)(feats + (size_t)rj * 64);
            else if (part == 1) src = (const float4*)(feats + (size_t)cj * 64);
            else                src = (const float4*)(edge_attr + (size_t)eid * 64);
            float4 v = src[q];
            int p = j >> 1, sub = j & 1;
            int k0 = part * 64 + q * 4;               // k0 % 4 == 0
            float* dst = (float*)(xw + p * 96 + (k0 >> 1)) + sub;
            dst[0] = v.x; dst[2] = v.y; dst[4] = v.z; dst[6] = v.w;
        }
        __syncwarp();

        // GEMM1: acc[p][h] = (hidden[2p][col_h], hidden[2p+1][col_h]), col_h = lane+32h
        float2 b1v = sb1[lane];
        unsigned long long acc[4][2];
        #pragma unroll
        for (int p = 0; p < 4; p++) {
            acc[p][0] = splat2(b1v.x);
            acc[p][1] = splat2(b1v.y);
        }
        #pragma unroll 2
        for (int kk = 0; kk < 96; kk++) {
            float2 w0 = sW1[(2 * kk) * 32 + lane];
            float2 w1 = sW1[(2 * kk + 1) * 32 + lane];
            unsigned long long ws00 = splat2(w0.x);
            unsigned long long ws01 = splat2(w0.y);
            unsigned long long ws10 = splat2(w1.x);
            unsigned long long ws11 = splat2(w1.y);
            #pragma unroll
            for (int p = 0; p < 4; p++) {
                ulonglong2 xp = xw[p * 96 + kk];
                acc[p][0] = fma2(xp.x, ws00, acc[p][0]);
                acc[p][1] = fma2(xp.x, ws01, acc[p][1]);
                acc[p][0] = fma2(xp.y, ws10, acc[p][0]);
                acc[p][1] = fma2(xp.y, ws11, acc[p][1]);
            }
        }

        // ReLU + store hidden pair-interleaved
        #pragma unroll
        for (int p = 0; p < 4; p++) {
            #pragma unroll
            for (int h = 0; h < 2; h++) {
                float2 v = unpack2(acc[p][h]);
                v.x = fmaxf(v.x, 0.0f); v.y = fmaxf(v.y, 0.0f);
                int col = lane + 32 * h;
                float* dstf = (float*)(hw + p * 32 + (col >> 1));
                *(float2*)(dstf + 2 * (col & 1)) = v;
            }
        }
        __syncwarp();

        // GEMM2
        float2 b2v = sb2[lane];
        unsigned long long acc2[4][2];
        #pragma unroll
        for (int p = 0; p < 4; p++) {
            acc2[p][0] = splat2(b2v.x);
            acc2[p][1] = splat2(b2v.y);
        }
        #pragma unroll 2
        for (int kk = 0; kk < 32; kk++) {
            float2 w0 = sW2[(2 * kk) * 32 + lane];
            float2 w1 = sW2[(2 * kk + 1) * 32 + lane];
            unsigned long long ws00 = splat2(w0.x);
            unsigned long long ws01 = splat2(w0.y);
            unsigned long long ws10 = splat2(w1.x);
            unsigned long long ws11 = splat2(w1.y);
            #pragma unroll
            for (int p = 0; p < 4; p++) {
                ulonglong2 xp = hw[p * 32 + kk];
                acc2[p][0] = fma2(xp.x, ws00, acc2[p][0]);
                acc2[p][1] = fma2(xp.x, ws01, acc2[p][1]);
                acc2[p][0] = fma2(xp.y, ws10, acc2[p][0]);
                acc2[p][1] = fma2(xp.y, ws11, acc2[p][1]);
            }
        }

        // Epilogue: stores + atomic aggregation
        #pragma unroll
        for (int p = 0; p < 4; p++) {
            int c0 = __shfl_sync(0xffffffffu, c, 2 * p);
            int c1 = __shfl_sync(0xffffffffu, c, 2 * p + 1);
            #pragma unroll
            for (int h = 0; h < 2; h++) {
                float2 v = unpack2(acc2[p][h]);
                int col = lane + 32 * h;
                if (2 * p < nE) {
                    e_out[(size_t)(ebase + 2 * p) * 64 + col] = v.x;
                    atomicAdd(&g_agg[(size_t)c0 * 64 + col], v.x);
                }
                if (2 * p + 1 < nE) {
                    e_out[(size_t)(ebase + 2 * p + 1) * 64 + col] = v.y;
                    atomicAdd(&g_agg[(size_t)c1 * 64 + col], v.y);
                }
            }
            if (lane == 0) {
                if (2 * p < nE)     atomicAdd(&g_deg[c0], 1.0f);
                if (2 * p + 1 < nE) atomicAdd(&g_deg[c1], 1.0f);
            }
        }
        __syncwarp();
    }
}

// ---------------------------------------------------------------------------
// Kernel 2: node MLP (8 nodes per warp, f32x2 packed)
//
// Smem (floats), 128 threads:
//   sW1 float2[128][32] off 0      (8192 f)
//   sW2 float2[64][32]  off 8192   (4096 f)
//   sb1 off 12288 (64), sb2 off 12352 (64)
//   xw  ull2 [4w][4p][64] off 12416 (4096 f)
//   hw  ull2 [4w][4p][32] off 16512 (2048 f)
//   total 18560 f = 74240 B
// ---------------------------------------------------------------------------
#define NODE_SMEM_FLOATS 18560

__global__ void __launch_bounds__(128, 2) node_kernel(
    const float* __restrict__ feats,
    const float* __restrict__ W1n, const float* __restrict__ b1n,
    const float* __restrict__ W2n, const float* __restrict__ b2n,
    float* __restrict__ feats_out,
    int n_nodes)
{
    extern __shared__ float smem[];
    float2* sW1 = (float2*)smem;
    float2* sW2 = (float2*)(smem + 8192);
    float2* sb1 = (float2*)(smem + 12288);
    float2* sb2 = (float2*)(smem + 12352);

    int tid = threadIdx.x;
    for (int i = tid; i < 128 * 32; i += 128) {
        int k = i >> 5, l = i & 31;
        sW1[i] = make_float2(W1n[k * 64 + l], W1n[k * 64 + l + 32]);
    }
    for (int i = tid; i < 64 * 32; i += 128) {
        int k = i >> 5, l = i & 31;
        sW2[i] = make_float2(W2n[k * 64 + l], W2n[k * 64 + l + 32]);
    }
    if (tid < 32) {
        sb1[tid] = make_float2(b1n[tid], b1n[tid + 32]);
        sb2[tid] = make_float2(b2n[tid], b2n[tid + 32]);
    }
    __syncthreads();

    int warp = tid >> 5, lane = tid & 31;
    ulonglong2* xw = (ulonglong2*)(smem + 12416) + warp * 4 * 64;
    ulonglong2* hw = (ulonglong2*)(smem + 16512) + warp * 4 * 32;

    int nGroups = (n_nodes + 7) >> 3;
    int gwarp = blockIdx.x * 4 + warp;
    int wstride = gridDim.x * 4;

    for (int g = gwarp; g < nGroups; g += wstride) {
        int nbase = g * 8;
        int nN = min(8, n_nodes - nbase);

        float invd = 1.0f;
        if (lane < 8) {
            int nid = nbase + min(lane, nN - 1);
            invd = 1.0f / fmaxf(g_deg[nid], 1.0f);
        }

        // Gather: 8 nodes * 32 float4 = 256 float4
        for (int i = lane; i < 256; i += 32) {
            int j = i >> 5;
            int part = (i >> 4) & 1;
            int q = i & 15;
            int nid = nbase + min(j, nN - 1);
            float s = __shfl_sync(0xffffffffu, invd, j);
            float4 v;
            if (part == 0) {
                v = ((const float4*)(feats + (size_t)nid * 64))[q];
            } else {
                v = ((const float4*)(g_agg + (size_t)nid * 64))[q];
                v.x *= s; v.y *= s; v.z *= s; v.w *= s;
            }
            int p = j >> 1, sub = j & 1;
            int k0 = part * 64 + q * 4;
            float* dst = (float*)(xw + p * 64 + (k0 >> 1)) + sub;
            dst[0] = v.x; dst[2] = v.y; dst[4] = v.z; dst[6] = v.w;
        }
        __syncwarp();

        float2 b1v = sb1[lane];
        unsigned long long acc[4][2];
        #pragma unroll
        for (int p = 0; p < 4; p++) {
            acc[p][0] = splat2(b1v.x);
            acc[p][1] = splat2(b1v.y);
        }
        #pragma unroll 2
        for (int kk = 0; kk < 64; kk++) {
            float2 w0 = sW1[(2 * kk) * 32 + lane];
            float2 w1 = sW1[(2 * kk + 1) * 32 + lane];
            unsigned long long ws00 = splat2(w0.x);
            unsigned long long ws01 = splat2(w0.y);
            unsigned long long ws10 = splat2(w1.x);
            unsigned long long ws11 = splat2(w1.y);
            #pragma unroll
            for (int p = 0; p < 4; p++) {
                ulonglong2 xp = xw[p * 64 + kk];
                acc[p][0] = fma2(xp.x, ws00, acc[p][0]);
                acc[p][1] = fma2(xp.x, ws01, acc[p][1]);
                acc[p][0] = fma2(xp.y, ws10, acc[p][0]);
                acc[p][1] = fma2(xp.y, ws11, acc[p][1]);
            }
        }

        #pragma unroll
        for (int p = 0; p < 4; p++) {
            #pragma unroll
            for (int h = 0; h < 2; h++) {
                float2 v = unpack2(acc[p][h]);
                v.x = fmaxf(v.x, 0.0f); v.y = fmaxf(v.y, 0.0f);
                int col = lane + 32 * h;
                float* dstf = (float*)(hw + p * 32 + (col >> 1));
                *(float2*)(dstf + 2 * (col & 1)) = v;
            }
        }
        __syncwarp();

        float2 b2v = sb2[lane];
        unsigned long long acc2[4][2];
        #pragma unroll
        for (int p = 0; p < 4; p++) {
            acc2[p][0] = splat2(b2v.x);
            acc2[p][1] = splat2(b2v.y);
        }
        #pragma unroll 2
        for (int kk = 0; kk < 32; kk++) {
            float2 w0 = sW2[(2 * kk) * 32 + lane];
            float2 w1 = sW2[(2 * kk + 1) * 32 + lane];
            unsigned long long ws00 = splat2(w0.x);
            unsigned long long ws01 = splat2(w0.y);
            unsigned long long ws10 = splat2(w1.x);
            unsigned long long ws11 = splat2(w1.y);
            #pragma unroll
            for (int p = 0; p < 4; p++) {
                ulonglong2 xp = hw[p * 32 + kk];
                acc2[p][0] = fma2(xp.x, ws00, acc2[p][0]);
                acc2[p][1] = fma2(xp.x, ws01, acc2[p][1]);
                acc2[p][0] = fma2(xp.y, ws10, acc2[p][0]);
                acc2[p][1] = fma2(xp.y, ws11, acc2[p][1]);
            }
        }

        #pragma unroll
        for (int p = 0; p < 4; p++) {
            #pragma unroll
            for (int h = 0; h < 2; h++) {
                float2 v = unpack2(acc2[p][h]);
                int col = lane + 32 * h;
                if (2 * p < nN)
                    feats_out[(size_t)(nbase + 2 * p) * 64 + col] = v.x;
                if (2 * p + 1 < nN)
                    feats_out[(size_t)(nbase + 2 * p + 1) * 64 + col] = v.y;
            }
        }
        __syncwarp();
    }
}

// ---------------------------------------------------------------------------
extern "C" void kernel_launch(void* const* d_in, const int* in_sizes, int n_in,
                              void* d_out, int out_size) {
    const float* feats      = (const float*)d_in[0];
    const int*   edge_index = (const int*)d_in[1];
    const float* edge_attr  = (const float*)d_in[2];
    const float* W1e        = (const float*)d_in[3];
    const float* b1e        = (const float*)d_in[4];
    const float* W2e        = (const float*)d_in[5];
    const float* b2e        = (const float*)d_in[6];
    const float* W1n        = (const float*)d_in[7];
    const float* b1n        = (const float*)d_in[8];
    const float* W2n        = (const float*)d_in[9];
    const float* b2n        = (const float*)d_in[10];

    int n_nodes = in_sizes[0] / 64;
    int n_edges = in_sizes[2] / 64;

    float* out       = (float*)d_out;
    float* feats_out = out;                            // [n_nodes, 64]
    float* e_out     = out + (size_t)n_nodes * 64;     // [n_edges, 64]

    size_t edge_smem = EDGE_SMEM_FLOATS * sizeof(float);
    size_t node_smem = NODE_SMEM_FLOATS * sizeof(float);
    cudaFuncSetAttribute(edge_kernel, cudaFuncAttributeMaxDynamicSharedMemorySize, (int)edge_smem);
    cudaFuncSetAttribute(node_kernel, cudaFuncAttributeMaxDynamicSharedMemorySize, (int)node_smem);

    zero_kernel<<<1024, 256>>>(n_nodes);
    edge_kernel<<<296, 128, edge_smem>>>(feats, edge_index, edge_attr,
                                         W1e, b1e, W2e, b2e, e_out, n_edges);
    node_kernel<<<296, 128, node_smem>>>(feats, W1n, b1n, W2n, b2n,
                                         feats_out, n_nodes);
}

// round 5
// speedup vs baseline: 2.4934x; 2.4934x over previous
#include <cuda_runtime.h>
#include <cuda_bf16.h>
#include <cstdint>

#define MAX_NODES 50000

__device__ float g_agg[MAX_NODES * 64];
__device__ float g_deg[MAX_NODES];

// ---------------- helpers ----------------
__device__ __forceinline__ void mma16816(float d[4], const uint32_t a[4],
                                         const uint32_t b[2]) {
    asm("mma.sync.aligned.m16n8k16.row.col.f32.bf16.bf16.f32 "
        "{%0,%1,%2,%3}, {%4,%5,%6,%7}, {%8,%9}, {%0,%1,%2,%3};"
        : "+f"(d[0]), "+f"(d[1]), "+f"(d[2]), "+f"(d[3])
        : "r"(a[0]), "r"(a[1]), "r"(a[2]), "r"(a[3]), "r"(b[0]), "r"(b[1]));
}

// split pair of fp32 into bf16x2 hi and bf16x2 lo (lo = x - bf16(x))
__device__ __forceinline__ void split2(float x0, float x1,
                                       uint32_t& uh, uint32_t& ul) {
    __nv_bfloat162 bh = __floats2bfloat162_rn(x0, x1);   // x0 -> low half
    float2 back = __bfloat1622float2(bh);
    __nv_bfloat162 bl = __floats2bfloat162_rn(x0 - back.x, x1 - back.y);
    uh = *(uint32_t*)&bh;
    ul = *(uint32_t*)&bl;
}

__device__ __forceinline__ void red_add2(float* addr, float a, float b) {
    asm volatile("red.global.add.v2.f32 [%0], {%1, %2};"
                 :: "l"(addr), "f"(a), "f"(b) : "memory");
}

// ---------------- kernel 0: zero scratch ----------------
__global__ void zero_kernel(int n_nodes) {
    int i = blockIdx.x * blockDim.x + threadIdx.x;
    int stride = gridDim.x * blockDim.x;
    int tot = n_nodes * 64;
    for (int k = i; k < tot; k += stride) g_agg[k] = 0.0f;
    for (int k = i; k < n_nodes; k += stride) g_deg[k] = 0.0f;
}

// ======================= edge kernel =======================
// A rows padded to 200 bf16 (100 words, 100%32=4 -> conflict-free frag LDS)
// H rows padded to 72 bf16 (36 words)
// smem byte offsets:
#define E_SA_HI   0u
#define E_SA_LO   51200u
#define E_SW1_HI  102400u
#define E_SW1_LO  128000u
#define E_SH_HI   153600u
#define E_SH_LO   172032u
#define E_SW2_HI  190464u
#define E_SW2_LO  199680u
#define E_BIAS1   208896u
#define E_BIAS2   209152u
#define E_SC      209408u
#define E_SMEM    209920u

__global__ void __launch_bounds__(256, 1) edge_kernel(
    const float* __restrict__ feats,
    const int* __restrict__ edge_index,
    const float* __restrict__ edge_attr,
    const float* __restrict__ W1e, const float* __restrict__ b1e,
    const float* __restrict__ W2e, const float* __restrict__ b2e,
    float* __restrict__ e_out,
    int n_edges)
{
    extern __shared__ char smem[];
    uint32_t* sA_hi  = (uint32_t*)(smem + E_SA_HI);    // [128][100] words
    uint32_t* sA_lo  = (uint32_t*)(smem + E_SA_LO);
    uint32_t* sW1_hi = (uint32_t*)(smem + E_SW1_HI);   // [64][100]
    uint32_t* sW1_lo = (uint32_t*)(smem + E_SW1_LO);
    uint32_t* sH_hi  = (uint32_t*)(smem + E_SH_HI);    // [128][36]
    uint32_t* sH_lo  = (uint32_t*)(smem + E_SH_LO);
    uint32_t* sW2_hi = (uint32_t*)(smem + E_SW2_HI);   // [64][36]
    uint32_t* sW2_lo = (uint32_t*)(smem + E_SW2_LO);
    float* bias1 = (float*)(smem + E_BIAS1);
    float* bias2 = (float*)(smem + E_BIAS2);
    int*   sc    = (int*)(smem + E_SC);

    int tid = threadIdx.x;

    // ---- stage weights (once): sW[n][k] hi/lo ----
    for (int i = tid; i < 192 * 64; i += 256) {
        int k = i >> 6, n = i & 63;
        float w = W1e[i];
        __nv_bfloat16 wh = __float2bfloat16_rn(w);
        __nv_bfloat16 wl = __float2bfloat16_rn(w - __bfloat162float(wh));
        ((__nv_bfloat16*)sW1_hi)[n * 200 + k] = wh;
        ((__nv_bfloat16*)sW1_lo)[n * 200 + k] = wl;
    }
    for (int i = tid; i < 64 * 64; i += 256) {
        int k = i >> 6, n = i & 63;
        float w = W2e[i];
        __nv_bfloat16 wh = __float2bfloat16_rn(w);
        __nv_bfloat16 wl = __float2bfloat16_rn(w - __bfloat162float(wh));
        ((__nv_bfloat16*)sW2_hi)[n * 72 + k] = wh;
        ((__nv_bfloat16*)sW2_lo)[n * 72 + k] = wl;
    }
    if (tid < 64) {
        bias1[tid] = b1e[tid];
        bias2[tid] = b2e[tid];
    }
    __syncthreads();

    const int warp = tid >> 5, lane = tid & 31;
    const int g = lane >> 2, t = lane & 3;
    const int wr = warp << 4;
    const int row = tid >> 1, half = tid & 1;

    int nTiles = (n_edges + 127) >> 7;

    for (int tile = blockIdx.x; tile < nTiles; tile += gridDim.x) {
        int ebase = tile << 7;

        // ---- gather (warp-private rows) ----
        {
            int er = ebase + row;
            bool v = er < n_edges;
            int eid = v ? er : (n_edges - 1);
            int2 rc = ((const int2*)edge_index)[eid];
            if (half == 0) {
                sc[row] = rc.y;
                if (v) atomicAdd(&g_deg[rc.y], 1.0f);
            }
            const float4* fr = (const float4*)(feats + (size_t)rc.x * 64);
            const float4* fc = (const float4*)(feats + (size_t)rc.y * 64);
            const float4* fe = (const float4*)(edge_attr + (size_t)eid * 64);
            #pragma unroll
            for (int cc = 0; cc < 12; cc++) {
                int col = half * 96 + cc * 8;
                float4 va, vb;
                if (col < 64)       va = fr[col >> 2];
                else if (col < 128) va = fc[(col - 64) >> 2];
                else                va = fe[(col - 128) >> 2];
                int col2 = col + 4;
                if (col2 < 64)       vb = fr[col2 >> 2];
                else if (col2 < 128) vb = fc[(col2 - 64) >> 2];
                else                 vb = fe[(col2 - 128) >> 2];
                uint4 uh, ul;
                split2(va.x, va.y, uh.x, ul.x);
                split2(va.z, va.w, uh.y, ul.y);
                split2(vb.x, vb.y, uh.z, ul.z);
                split2(vb.z, vb.w, uh.w, ul.w);
                int widx = row * 100 + (col >> 1);
                *(uint4*)(sA_hi + widx) = uh;
                *(uint4*)(sA_lo + widx) = ul;
            }
        }
        __syncwarp();

        // ---- GEMM1: D[16x64] per warp, K=192, 3-pass split ----
        float d[8][4];
        #pragma unroll
        for (int i = 0; i < 8; i++)
            #pragma unroll
            for (int j = 0; j < 4; j++) d[i][j] = 0.0f;

        #pragma unroll 1
        for (int kt = 0; kt < 12; kt++) {
            int ab = (wr + g) * 100 + kt * 8 + t;
            uint32_t ah[4], al[4];
            ah[0] = sA_hi[ab];       ah[1] = sA_hi[ab + 800];
            ah[2] = sA_hi[ab + 4];   ah[3] = sA_hi[ab + 804];
            al[0] = sA_lo[ab];       al[1] = sA_lo[ab + 800];
            al[2] = sA_lo[ab + 4];   al[3] = sA_lo[ab + 804];
            #pragma unroll
            for (int nt = 0; nt < 8; nt++) {
                int bb = (nt * 8 + g) * 100 + kt * 8 + t;
                uint32_t bh[2] = { sW1_hi[bb], sW1_hi[bb + 4] };
                uint32_t bl[2] = { sW1_lo[bb], sW1_lo[bb + 4] };
                mma16816(d[nt], ah, bh);
                mma16816(d[nt], ah, bl);
                mma16816(d[nt], al, bh);
            }
        }

        // ---- epilogue 1: h = relu(D + b1) -> sH hi/lo ----
        #pragma unroll
        for (int nt = 0; nt < 8; nt++) {
            int c0 = nt * 8 + 2 * t;
            float bb0 = bias1[c0], bb1 = bias1[c0 + 1];
            float h0 = fmaxf(d[nt][0] + bb0, 0.f), h1 = fmaxf(d[nt][1] + bb1, 0.f);
            float h2 = fmaxf(d[nt][2] + bb0, 0.f), h3 = fmaxf(d[nt][3] + bb1, 0.f);
            uint32_t uh, ul;
            int w0 = (wr + g) * 36 + nt * 4 + t;
            split2(h0, h1, uh, ul);
            sH_hi[w0] = uh; sH_lo[w0] = ul;
            split2(h2, h3, uh, ul);
            sH_hi[w0 + 288] = uh; sH_lo[w0 + 288] = ul;
        }
        __syncwarp();

        // ---- GEMM2: K=64 ----
        float d2[8][4];
        #pragma unroll
        for (int i = 0; i < 8; i++)
            #pragma unroll
            for (int j = 0; j < 4; j++) d2[i][j] = 0.0f;

        #pragma unroll 1
        for (int kt = 0; kt < 4; kt++) {
            int ab = (wr + g) * 36 + kt * 8 + t;
            uint32_t ah[4], al[4];
            ah[0] = sH_hi[ab];       ah[1] = sH_hi[ab + 288];
            ah[2] = sH_hi[ab + 4];   ah[3] = sH_hi[ab + 292];
            al[0] = sH_lo[ab];       al[1] = sH_lo[ab + 288];
            al[2] = sH_lo[ab + 4];   al[3] = sH_lo[ab + 292];
            #pragma unroll
            for (int nt = 0; nt < 8; nt++) {
                int bb = (nt * 8 + g) * 36 + kt * 8 + t;
                uint32_t bh[2] = { sW2_hi[bb], sW2_hi[bb + 4] };
                uint32_t bl[2] = { sW2_lo[bb], sW2_lo[bb + 4] };
                mma16816(d2[nt], ah, bh);
                mma16816(d2[nt], ah, bl);
                mma16816(d2[nt], al, bh);
            }
        }

        // ---- epilogue 2: e = D2 + b2 -> e_out + vector red to g_agg ----
        {
            int r0 = ebase + wr + g, r1 = r0 + 8;
            bool v0 = r0 < n_edges, v1 = r1 < n_edges;
            int ca = sc[wr + g], cb = sc[wr + 8 + g];
            #pragma unroll
            for (int nt = 0; nt < 8; nt++) {
                int c0 = nt * 8 + 2 * t;
                float bb0 = bias2[c0], bb1 = bias2[c0 + 1];
                float e0 = d2[nt][0] + bb0, e1 = d2[nt][1] + bb1;
                float e2 = d2[nt][2] + bb0, e3 = d2[nt][3] + bb1;
                if (v0) {
                    *(float2*)(e_out + (size_t)r0 * 64 + c0) = make_float2(e0, e1);
                    red_add2(g_agg + (size_t)ca * 64 + c0, e0, e1);
                }
                if (v1) {
                    *(float2*)(e_out + (size_t)r1 * 64 + c0) = make_float2(e2, e3);
                    red_add2(g_agg + (size_t)cb * 64 + c0, e2, e3);
                }
            }
        }
        __syncwarp();
    }
}

// ======================= node kernel =======================
// A rows padded to 136 bf16 (68 words), H rows 72 bf16 (36 words)
#define N_SA_HI   0u
#define N_SA_LO   34816u
#define N_SW1_HI  69632u
#define N_SW1_LO  87040u
#define N_SH_HI   104448u
#define N_SH_LO   122880u
#define N_SW2_HI  141312u
#define N_SW2_LO  150528u
#define N_BIAS1   159744u
#define N_BIAS2   160000u
#define N_SMEM    160256u

__global__ void __launch_bounds__(256, 1) node_kernel(
    const float* __restrict__ feats,
    const float* __restrict__ W1n, const float* __restrict__ b1n,
    const float* __restrict__ W2n, const float* __restrict__ b2n,
    float* __restrict__ feats_out,
    int n_nodes)
{
    extern __shared__ char smem[];
    uint32_t* sA_hi  = (uint32_t*)(smem + N_SA_HI);    // [128][68]
    uint32_t* sA_lo  = (uint32_t*)(smem + N_SA_LO);
    uint32_t* sW1_hi = (uint32_t*)(smem + N_SW1_HI);   // [64][68]
    uint32_t* sW1_lo = (uint32_t*)(smem + N_SW1_LO);
    uint32_t* sH_hi  = (uint32_t*)(smem + N_SH_HI);    // [128][36]
    uint32_t* sH_lo  = (uint32_t*)(smem + N_SH_LO);
    uint32_t* sW2_hi = (uint32_t*)(smem + N_SW2_HI);   // [64][36]
    uint32_t* sW2_lo = (uint32_t*)(smem + N_SW2_LO);
    float* bias1 = (float*)(smem + N_BIAS1);
    float* bias2 = (float*)(smem + N_BIAS2);

    int tid = threadIdx.x;

    for (int i = tid; i < 128 * 64; i += 256) {
        int k = i >> 6, n = i & 63;
        float w = W1n[i];
        __nv_bfloat16 wh = __float2bfloat16_rn(w);
        __nv_bfloat16 wl = __float2bfloat16_rn(w - __bfloat162float(wh));
        ((__nv_bfloat16*)sW1_hi)[n * 136 + k] = wh;
        ((__nv_bfloat16*)sW1_lo)[n * 136 + k] = wl;
    }
    for (int i = tid; i < 64 * 64; i += 256) {
        int k = i >> 6, n = i & 63;
        float w = W2n[i];
        __nv_bfloat16 wh = __float2bfloat16_rn(w);
        __nv_bfloat16 wl = __float2bfloat16_rn(w - __bfloat162float(wh));
        ((__nv_bfloat16*)sW2_hi)[n * 72 + k] = wh;
        ((__nv_bfloat16*)sW2_lo)[n * 72 + k] = wl;
    }
    if (tid < 64) {
        bias1[tid] = b1n[tid];
        bias2[tid] = b2n[tid];
    }
    __syncthreads();

    const int warp = tid >> 5, lane = tid & 31;
    const int g = lane >> 2, t = lane & 3;
    const int wr = warp << 4;
    const int row = tid >> 1, half = tid & 1;

    int nTiles = (n_nodes + 127) >> 7;

    for (int tile = blockIdx.x; tile < nTiles; tile += gridDim.x) {
        int nbase = tile << 7;

        // ---- gather h = [feats | agg/max(deg,1)] ----
        {
            int nr = nbase + row;
            int nid = nr < n_nodes ? nr : (n_nodes - 1);
            const float4* src;
            float scale;
            if (half == 0) {
                src = (const float4*)(feats + (size_t)nid * 64);
                scale = 1.0f;
            } else {
                src = (const float4*)(g_agg + (size_t)nid * 64);
                scale = 1.0f / fmaxf(g_deg[nid], 1.0f);
            }
            #pragma unroll
            for (int cc = 0; cc < 8; cc++) {
                float4 va = src[cc * 2], vb = src[cc * 2 + 1];
                va.x *= scale; va.y *= scale; va.z *= scale; va.w *= scale;
                vb.x *= scale; vb.y *= scale; vb.z *= scale; vb.w *= scale;
                uint4 uh, ul;
                split2(va.x, va.y, uh.x, ul.x);
                split2(va.z, va.w, uh.y, ul.y);
                split2(vb.x, vb.y, uh.z, ul.z);
                split2(vb.z, vb.w, uh.w, ul.w);
                int col = half * 64 + cc * 8;
                int widx = row * 68 + (col >> 1);
                *(uint4*)(sA_hi + widx) = uh;
                *(uint4*)(sA_lo + widx) = ul;
            }
        }
        __syncwarp();

        // ---- GEMM1: K=128 ----
        float d[8][4];
        #pragma unroll
        for (int i = 0; i < 8; i++)
            #pragma unroll
            for (int j = 0; j < 4; j++) d[i][j] = 0.0f;

        #pragma unroll 1
        for (int kt = 0; kt < 8; kt++) {
            int ab = (wr + g) * 68 + kt * 8 + t;
            uint32_t ah[4], al[4];
            ah[0] = sA_hi[ab];       ah[1] = sA_hi[ab + 544];
            ah[2] = sA_hi[ab + 4];   ah[3] = sA_hi[ab + 548];
            al[0] = sA_lo[ab];       al[1] = sA_lo[ab + 544];
            al[2] = sA_lo[ab + 4];   al[3] = sA_lo[ab + 548];
            #pragma unroll
            for (int nt = 0; nt < 8; nt++) {
                int bb = (nt * 8 + g) * 68 + kt * 8 + t;
                uint32_t bh[2] = { sW1_hi[bb], sW1_hi[bb + 4] };
                uint32_t bl[2] = { sW1_lo[bb], sW1_lo[bb + 4] };
                mma16816(d[nt], ah, bh);
                mma16816(d[nt], ah, bl);
                mma16816(d[nt], al, bh);
            }
        }

        // ---- epilogue 1 ----
        #pragma unroll
        for (int nt = 0; nt < 8; nt++) {
            int c0 = nt * 8 + 2 * t;
            float bb0 = bias1[c0], bb1 = bias1[c0 + 1];
            float h0 = fmaxf(d[nt][0] + bb0, 0.f), h1 = fmaxf(d[nt][1] + bb1, 0.f);
            float h2 = fmaxf(d[nt][2] + bb0, 0.f), h3 = fmaxf(d[nt][3] + bb1, 0.f);
            uint32_t uh, ul;
            int w0 = (wr + g) * 36 + nt * 4 + t;
            split2(h0, h1, uh, ul);
            sH_hi[w0] = uh; sH_lo[w0] = ul;
            split2(h2, h3, uh, ul);
            sH_hi[w0 + 288] = uh; sH_lo[w0 + 288] = ul;
        }
        __syncwarp();

        // ---- GEMM2: K=64 ----
        float d2[8][4];
        #pragma unroll
        for (int i = 0; i < 8; i++)
            #pragma unroll
            for (int j = 0; j < 4; j++) d2[i][j] = 0.0f;

        #pragma unroll 1
        for (int kt = 0; kt < 4; kt++) {
            int ab = (wr + g) * 36 + kt * 8 + t;
            uint32_t ah[4], al[4];
            ah[0] = sH_hi[ab];       ah[1] = sH_hi[ab + 288];
            ah[2] = sH_hi[ab + 4];   ah[3] = sH_hi[ab + 292];
            al[0] = sH_lo[ab];       al[1] = sH_lo[ab + 288];
            al[2] = sH_lo[ab + 4];   al[3] = sH_lo[ab + 292];
            #pragma unroll
            for (int nt = 0; nt < 8; nt++) {
                int bb = (nt * 8 + g) * 36 + kt * 8 + t;
                uint32_t bh[2] = { sW2_hi[bb], sW2_hi[bb + 4] };
                uint32_t bl[2] = { sW2_lo[bb], sW2_lo[bb + 4] };
                mma16816(d2[nt], ah, bh);
                mma16816(d2[nt], ah, bl);
                mma16816(d2[nt], al, bh);
            }
        }

        // ---- epilogue 2: feats_out = D2 + b2 ----
        {
            int r0 = nbase + wr + g, r1 = r0 + 8;
            bool v0 = r0 < n_nodes, v1 = r1 < n_nodes;
            #pragma unroll
            for (int nt = 0; nt < 8; nt++) {
                int c0 = nt * 8 + 2 * t;
                float bb0 = bias2[c0], bb1 = bias2[c0 + 1];
                if (v0)
                    *(float2*)(feats_out + (size_t)r0 * 64 + c0) =
                        make_float2(d2[nt][0] + bb0, d2[nt][1] + bb1);
                if (v1)
                    *(float2*)(feats_out + (size_t)r1 * 64 + c0) =
                        make_float2(d2[nt][2] + bb0, d2[nt][3] + bb1);
            }
        }
        __syncwarp();
    }
}

// ======================= launch =======================
extern "C" void kernel_launch(void* const* d_in, const int* in_sizes, int n_in,
                              void* d_out, int out_size) {
    const float* feats      = (const float*)d_in[0];
    const int*   edge_index = (const int*)d_in[1];
    const float* edge_attr  = (const float*)d_in[2];
    const float* W1e        = (const float*)d_in[3];
    const float* b1e        = (const float*)d_in[4];
    const float* W2e        = (const float*)d_in[5];
    const float* b2e        = (const float*)d_in[6];
    const float* W1n        = (const float*)d_in[7];
    const float* b1n        = (const float*)d_in[8];
    const float* W2n        = (const float*)d_in[9];
    const float* b2n        = (const float*)d_in[10];

    int n_nodes = in_sizes[0] / 64;
    int n_edges = in_sizes[2] / 64;

    float* out       = (float*)d_out;
    float* feats_out = out;                          // [n_nodes, 64]
    float* e_out     = out + (size_t)n_nodes * 64;   // [n_edges, 64]

    cudaFuncSetAttribute(edge_kernel, cudaFuncAttributeMaxDynamicSharedMemorySize, E_SMEM);
    cudaFuncSetAttribute(node_kernel, cudaFuncAttributeMaxDynamicSharedMemorySize, N_SMEM);

    zero_kernel<<<1024, 256>>>(n_nodes);
    edge_kernel<<<148, 256, E_SMEM>>>(feats, edge_index, edge_attr,
                                      W1e, b1e, W2e, b2e, e_out, n_edges);
    node_kernel<<<148, 256, N_SMEM>>>(feats, W1n, b1n, W2n, b2n,
                                      feats_out, n_nodes);
}

// round 6
// speedup vs baseline: 3.2705x; 1.3117x over previous
#include <cuda_runtime.h>
#include <cuda_bf16.h>
#include <cstdint>

#define MAX_NODES 50000

__device__ float g_agg[MAX_NODES * 64];
__device__ float g_deg[MAX_NODES];
__device__ float g_P[MAX_NODES * 128];   // P[v] = feats[v] @ [W1e[0:64]||W1e[64:128]]

// ---------------- helpers ----------------
__device__ __forceinline__ void mma16816(float d[4], const uint32_t a[4],
                                         const uint32_t b[2]) {
    asm("mma.sync.aligned.m16n8k16.row.col.f32.bf16.bf16.f32 "
        "{%0,%1,%2,%3}, {%4,%5,%6,%7}, {%8,%9}, {%0,%1,%2,%3};"
        : "+f"(d[0]), "+f"(d[1]), "+f"(d[2]), "+f"(d[3])
        : "r"(a[0]), "r"(a[1]), "r"(a[2]), "r"(a[3]), "r"(b[0]), "r"(b[1]));
}

__device__ __forceinline__ void split2(float x0, float x1,
                                       uint32_t& uh, uint32_t& ul) {
    __nv_bfloat162 bh = __floats2bfloat162_rn(x0, x1);
    float2 back = __bfloat1622float2(bh);
    __nv_bfloat162 bl = __floats2bfloat162_rn(x0 - back.x, x1 - back.y);
    uh = *(uint32_t*)&bh;
    ul = *(uint32_t*)&bl;
}

__device__ __forceinline__ void red_add2(float* addr, float a, float b) {
    asm volatile("red.global.add.v2.f32 [%0], {%1, %2};"
                 :: "l"(addr), "f"(a), "f"(b) : "memory");
}

// ---------------- kernel 0: zero scratch ----------------
__global__ void zero_kernel(int n_nodes) {
    int i = blockIdx.x * blockDim.x + threadIdx.x;
    int stride = gridDim.x * blockDim.x;
    int tot = n_nodes * 64;
    for (int k = i; k < tot; k += stride) g_agg[k] = 0.0f;
    for (int k = i; k < n_nodes; k += stride) g_deg[k] = 0.0f;
}

// ======================= P precompute kernel =======================
// P[v][0:128] = feats[v] @ [W1e[0:64,:] || W1e[64:128,:]]   (no bias)
// smem: sA hi/lo [128 rows][36 words], sW hi/lo [128 n][36 words]
#define P_SA_HI 0u
#define P_SA_LO 18432u
#define P_SW_HI 36864u
#define P_SW_LO 55296u
#define P_SMEM  73728u

__global__ void __launch_bounds__(256, 2) pnode_kernel(
    const float* __restrict__ feats,
    const float* __restrict__ W1e,
    int n_nodes)
{
    extern __shared__ char smem[];
    uint32_t* sA_hi = (uint32_t*)(smem + P_SA_HI);
    uint32_t* sA_lo = (uint32_t*)(smem + P_SA_LO);
    uint32_t* sW_hi = (uint32_t*)(smem + P_SW_HI);
    uint32_t* sW_lo = (uint32_t*)(smem + P_SW_LO);

    int tid = threadIdx.x;
    for (int i = tid; i < 128 * 64; i += 256) {
        int n = i & 127, k = i >> 7;
        float w = (n < 64) ? W1e[k * 64 + n] : W1e[(64 + k) * 64 + (n - 64)];
        __nv_bfloat16 wh = __float2bfloat16_rn(w);
        __nv_bfloat16 wl = __float2bfloat16_rn(w - __bfloat162float(wh));
        ((__nv_bfloat16*)sW_hi)[n * 72 + k] = wh;
        ((__nv_bfloat16*)sW_lo)[n * 72 + k] = wl;
    }
    __syncthreads();

    const int warp = tid >> 5, lane = tid & 31;
    const int g = lane >> 2, t = lane & 3;
    const int wr = warp << 4;
    const int row = tid >> 1, half = tid & 1;

    int nTiles = (n_nodes + 127) >> 7;

    for (int tile = blockIdx.x; tile < nTiles; tile += gridDim.x) {
        int nbase = tile << 7;
        {
            int nr = nbase + row;
            int nid = nr < n_nodes ? nr : (n_nodes - 1);
            const float4* src = (const float4*)(feats + (size_t)nid * 64) + half * 8;
            #pragma unroll
            for (int cc = 0; cc < 4; cc++) {
                float4 va = src[cc * 2], vb = src[cc * 2 + 1];
                uint4 uh, ul;
                split2(va.x, va.y, uh.x, ul.x);
                split2(va.z, va.w, uh.y, ul.y);
                split2(vb.x, vb.y, uh.z, ul.z);
                split2(vb.z, vb.w, uh.w, ul.w);
                int col = half * 32 + cc * 8;
                int widx = row * 36 + (col >> 1);
                *(uint4*)(sA_hi + widx) = uh;
                *(uint4*)(sA_lo + widx) = ul;
            }
        }
        __syncwarp();

        float d[16][4];
        #pragma unroll
        for (int i = 0; i < 16; i++)
            #pragma unroll
            for (int j = 0; j < 4; j++) d[i][j] = 0.0f;

        #pragma unroll 1
        for (int kt = 0; kt < 4; kt++) {
            int ab = (wr + g) * 36 + kt * 8 + t;
            uint32_t ah[4], al[4];
            ah[0] = sA_hi[ab];       ah[1] = sA_hi[ab + 288];
            ah[2] = sA_hi[ab + 4];   ah[3] = sA_hi[ab + 292];
            al[0] = sA_lo[ab];       al[1] = sA_lo[ab + 288];
            al[2] = sA_lo[ab + 4];   al[3] = sA_lo[ab + 292];
            #pragma unroll
            for (int nt = 0; nt < 16; nt++) {
                int bb = (nt * 8 + g) * 36 + kt * 8 + t;
                uint32_t bh[2] = { sW_hi[bb], sW_hi[bb + 4] };
                uint32_t bl[2] = { sW_lo[bb], sW_lo[bb + 4] };
                mma16816(d[nt], ah, bh);
                mma16816(d[nt], ah, bl);
                mma16816(d[nt], al, bh);
            }
        }

        {
            int r0 = nbase + wr + g, r1 = r0 + 8;
            bool v0 = r0 < n_nodes, v1 = r1 < n_nodes;
            #pragma unroll
            for (int nt = 0; nt < 16; nt++) {
                int c0 = nt * 8 + 2 * t;
                if (v0) *(float2*)(g_P + (size_t)r0 * 128 + c0) =
                            make_float2(d[nt][0], d[nt][1]);
                if (v1) *(float2*)(g_P + (size_t)r1 * 128 + c0) =
                            make_float2(d[nt][2], d[nt][3]);
            }
        }
        __syncwarp();
    }
}

// ======================= edge kernel =======================
// hidden = relu(edge_attr@W1c + P[r][0:64] + P[c][64:128] + b1); e = hidden@W2 + b2
#define E_SA_HI   0u
#define E_SA_LO   18432u
#define E_SW1_HI  36864u
#define E_SW1_LO  46080u
#define E_SH_HI   55296u
#define E_SH_LO   73728u
#define E_SW2_HI  92160u
#define E_SW2_LO  101376u
#define E_BIAS1   110592u
#define E_BIAS2   110848u
#define E_SR      111104u
#define E_SC      111616u
#define E_SMEM    112128u

__global__ void __launch_bounds__(256, 2) edge_kernel(
    const float* __restrict__ feats,
    const int* __restrict__ edge_index,
    const float* __restrict__ edge_attr,
    const float* __restrict__ W1e, const float* __restrict__ b1e,
    const float* __restrict__ W2e, const float* __restrict__ b2e,
    float* __restrict__ e_out,
    int n_edges)
{
    extern __shared__ char smem[];
    uint32_t* sA_hi  = (uint32_t*)(smem + E_SA_HI);    // [128][36] edge_attr
    uint32_t* sA_lo  = (uint32_t*)(smem + E_SA_LO);
    uint32_t* sW1_hi = (uint32_t*)(smem + E_SW1_HI);   // [64][36]  W1e rows 128..191
    uint32_t* sW1_lo = (uint32_t*)(smem + E_SW1_LO);
    uint32_t* sH_hi  = (uint32_t*)(smem + E_SH_HI);    // [128][36]
    uint32_t* sH_lo  = (uint32_t*)(smem + E_SH_LO);
    uint32_t* sW2_hi = (uint32_t*)(smem + E_SW2_HI);   // [64][36]
    uint32_t* sW2_lo = (uint32_t*)(smem + E_SW2_LO);
    float* bias1 = (float*)(smem + E_BIAS1);
    float* bias2 = (float*)(smem + E_BIAS2);
    int*   sr    = (int*)(smem + E_SR);
    int*   sc    = (int*)(smem + E_SC);

    int tid = threadIdx.x;

    for (int i = tid; i < 64 * 64; i += 256) {
        int k = i >> 6, n = i & 63;
        float w = W1e[(128 + k) * 64 + n];
        __nv_bfloat16 wh = __float2bfloat16_rn(w);
        __nv_bfloat16 wl = __float2bfloat16_rn(w - __bfloat162float(wh));
        ((__nv_bfloat16*)sW1_hi)[n * 72 + k] = wh;
        ((__nv_bfloat16*)sW1_lo)[n * 72 + k] = wl;
    }
    for (int i = tid; i < 64 * 64; i += 256) {
        int k = i >> 6, n = i & 63;
        float w = W2e[i];
        __nv_bfloat16 wh = __float2bfloat16_rn(w);
        __nv_bfloat16 wl = __float2bfloat16_rn(w - __bfloat162float(wh));
        ((__nv_bfloat16*)sW2_hi)[n * 72 + k] = wh;
        ((__nv_bfloat16*)sW2_lo)[n * 72 + k] = wl;
    }
    if (tid < 64) {
        bias1[tid] = b1e[tid];
        bias2[tid] = b2e[tid];
    }
    __syncthreads();

    const int warp = tid >> 5, lane = tid & 31;
    const int g = lane >> 2, t = lane & 3;
    const int wr = warp << 4;
    const int row = tid >> 1, half = tid & 1;

    int nTiles = (n_edges + 127) >> 7;

    for (int tile = blockIdx.x; tile < nTiles; tile += gridDim.x) {
        int ebase = tile << 7;

        // ---- gather edge_attr + indices (warp-private rows) ----
        {
            int er = ebase + row;
            bool v = er < n_edges;
            int eid = v ? er : (n_edges - 1);
            if (half == 0) {
                int2 rc = ((const int2*)edge_index)[eid];
                sr[row] = rc.x;
                sc[row] = rc.y;
                if (v) atomicAdd(&g_deg[rc.y], 1.0f);
            }
            const float4* fe = (const float4*)(edge_attr + (size_t)eid * 64) + half * 8;
            #pragma unroll
            for (int cc = 0; cc < 4; cc++) {
                float4 va = fe[cc * 2], vb = fe[cc * 2 + 1];
                uint4 uh, ul;
                split2(va.x, va.y, uh.x, ul.x);
                split2(va.z, va.w, uh.y, ul.y);
                split2(vb.x, vb.y, uh.z, ul.z);
                split2(vb.z, vb.w, uh.w, ul.w);
                int col = half * 32 + cc * 8;
                int widx = row * 36 + (col >> 1);
                *(uint4*)(sA_hi + widx) = uh;
                *(uint4*)(sA_lo + widx) = ul;
            }
        }
        __syncwarp();

        // ---- GEMM1: edge_attr @ W1c, K=64 ----
        float d[8][4];
        #pragma unroll
        for (int i = 0; i < 8; i++)
            #pragma unroll
            for (int j = 0; j < 4; j++) d[i][j] = 0.0f;

        #pragma unroll 1
        for (int kt = 0; kt < 4; kt++) {
            int ab = (wr + g) * 36 + kt * 8 + t;
            uint32_t ah[4], al[4];
            ah[0] = sA_hi[ab];       ah[1] = sA_hi[ab + 288];
            ah[2] = sA_hi[ab + 4];   ah[3] = sA_hi[ab + 292];
            al[0] = sA_lo[ab];       al[1] = sA_lo[ab + 288];
            al[2] = sA_lo[ab + 4];   al[3] = sA_lo[ab + 292];
            #pragma unroll
            for (int nt = 0; nt < 8; nt++) {
                int bb = (nt * 8 + g) * 36 + kt * 8 + t;
                uint32_t bh[2] = { sW1_hi[bb], sW1_hi[bb + 4] };
                uint32_t bl[2] = { sW1_lo[bb], sW1_lo[bb + 4] };
                mma16816(d[nt], ah, bh);
                mma16816(d[nt], ah, bl);
                mma16816(d[nt], al, bh);
            }
        }

        // ---- epilogue 1: h = relu(d + P[r][c] + P[c][64+c] + b1) -> sH ----
        {
            int rr0 = sr[wr + g],     cc0 = sc[wr + g];
            int rr1 = sr[wr + 8 + g], cc1 = sc[wr + 8 + g];
            const float* P0r = g_P + (size_t)rr0 * 128;
            const float* P0c = g_P + (size_t)cc0 * 128 + 64;
            const float* P1r = g_P + (size_t)rr1 * 128;
            const float* P1c = g_P + (size_t)cc1 * 128 + 64;
            #pragma unroll
            for (int nt = 0; nt < 8; nt++) {
                int c0 = nt * 8 + 2 * t;
                float2 pa = *(const float2*)(P0r + c0);
                float2 pb = *(const float2*)(P0c + c0);
                float2 pc_ = *(const float2*)(P1r + c0);
                float2 pd = *(const float2*)(P1c + c0);
                float bb0 = bias1[c0], bb1 = bias1[c0 + 1];
                float h0 = fmaxf(d[nt][0] + pa.x + pb.x + bb0, 0.f);
                float h1 = fmaxf(d[nt][1] + pa.y + pb.y + bb1, 0.f);
                float h2 = fmaxf(d[nt][2] + pc_.x + pd.x + bb0, 0.f);
                float h3 = fmaxf(d[nt][3] + pc_.y + pd.y + bb1, 0.f);
                uint32_t uh, ul;
                int w0 = (wr + g) * 36 + nt * 4 + t;
                split2(h0, h1, uh, ul);
                sH_hi[w0] = uh; sH_lo[w0] = ul;
                split2(h2, h3, uh, ul);
                sH_hi[w0 + 288] = uh; sH_lo[w0 + 288] = ul;
            }
        }
        __syncwarp();

        // ---- GEMM2: K=64 ----
        float d2[8][4];
        #pragma unroll
        for (int i = 0; i < 8; i++)
            #pragma unroll
            for (int j = 0; j < 4; j++) d2[i][j] = 0.0f;

        #pragma unroll 1
        for (int kt = 0; kt < 4; kt++) {
            int ab = (wr + g) * 36 + kt * 8 + t;
            uint32_t ah[4], al[4];
            ah[0] = sH_hi[ab];       ah[1] = sH_hi[ab + 288];
            ah[2] = sH_hi[ab + 4];   ah[3] = sH_hi[ab + 292];
            al[0] = sH_lo[ab];       al[1] = sH_lo[ab + 288];
            al[2] = sH_lo[ab + 4];   al[3] = sH_lo[ab + 292];
            #pragma unroll
            for (int nt = 0; nt < 8; nt++) {
                int bb = (nt * 8 + g) * 36 + kt * 8 + t;
                uint32_t bh[2] = { sW2_hi[bb], sW2_hi[bb + 4] };
                uint32_t bl[2] = { sW2_lo[bb], sW2_lo[bb + 4] };
                mma16816(d2[nt], ah, bh);
                mma16816(d2[nt], ah, bl);
                mma16816(d2[nt], al, bh);
            }
        }

        // ---- epilogue 2: e = D2 + b2 -> e_out + vector red to g_agg ----
        {
            int r0 = ebase + wr + g, r1 = r0 + 8;
            bool v0 = r0 < n_edges, v1 = r1 < n_edges;
            int ca = sc[wr + g], cb = sc[wr + 8 + g];
            #pragma unroll
            for (int nt = 0; nt < 8; nt++) {
                int c0 = nt * 8 + 2 * t;
                float bb0 = bias2[c0], bb1 = bias2[c0 + 1];
                float e0 = d2[nt][0] + bb0, e1 = d2[nt][1] + bb1;
                float e2 = d2[nt][2] + bb0, e3 = d2[nt][3] + bb1;
                if (v0) {
                    *(float2*)(e_out + (size_t)r0 * 64 + c0) = make_float2(e0, e1);
                    red_add2(g_agg + (size_t)ca * 64 + c0, e0, e1);
                }
                if (v1) {
                    *(float2*)(e_out + (size_t)r1 * 64 + c0) = make_float2(e2, e3);
                    red_add2(g_agg + (size_t)cb * 64 + c0, e2, e3);
                }
            }
        }
        __syncwarp();
    }
}

// ======================= node kernel (unchanged from R5) =======================
#define N_SA_HI   0u
#define N_SA_LO   34816u
#define N_SW1_HI  69632u
#define N_SW1_LO  87040u
#define N_SH_HI   104448u
#define N_SH_LO   122880u
#define N_SW2_HI  141312u
#define N_SW2_LO  150528u
#define N_BIAS1   159744u
#define N_BIAS2   160000u
#define N_SMEM    160256u

__global__ void __launch_bounds__(256, 1) node_kernel(
    const float* __restrict__ feats,
    const float* __restrict__ W1n, const float* __restrict__ b1n,
    const float* __restrict__ W2n, const float* __restrict__ b2n,
    float* __restrict__ feats_out,
    int n_nodes)
{
    extern __shared__ char smem[];
    uint32_t* sA_hi  = (uint32_t*)(smem + N_SA_HI);    // [128][68]
    uint32_t* sA_lo  = (uint32_t*)(smem + N_SA_LO);
    uint32_t* sW1_hi = (uint32_t*)(smem + N_SW1_HI);   // [64][68]
    uint32_t* sW1_lo = (uint32_t*)(smem + N_SW1_LO);
    uint32_t* sH_hi  = (uint32_t*)(smem + N_SH_HI);    // [128][36]
    uint32_t* sH_lo  = (uint32_t*)(smem + N_SH_LO);
    uint32_t* sW2_hi = (uint32_t*)(smem + N_SW2_HI);   // [64][36]
    uint32_t* sW2_lo = (uint32_t*)(smem + N_SW2_LO);
    float* bias1 = (float*)(smem + N_BIAS1);
    float* bias2 = (float*)(smem + N_BIAS2);

    int tid = threadIdx.x;

    for (int i = tid; i < 128 * 64; i += 256) {
        int k = i >> 6, n = i & 63;
        float w = W1n[i];
        __nv_bfloat16 wh = __float2bfloat16_rn(w);
        __nv_bfloat16 wl = __float2bfloat16_rn(w - __bfloat162float(wh));
        ((__nv_bfloat16*)sW1_hi)[n * 136 + k] = wh;
        ((__nv_bfloat16*)sW1_lo)[n * 136 + k] = wl;
    }
    for (int i = tid; i < 64 * 64; i += 256) {
        int k = i >> 6, n = i & 63;
        float w = W2n[i];
        __nv_bfloat16 wh = __float2bfloat16_rn(w);
        __nv_bfloat16 wl = __float2bfloat16_rn(w - __bfloat162float(wh));
        ((__nv_bfloat16*)sW2_hi)[n * 72 + k] = wh;
        ((__nv_bfloat16*)sW2_lo)[n * 72 + k] = wl;
    }
    if (tid < 64) {
        bias1[tid] = b1n[tid];
        bias2[tid] = b2n[tid];
    }
    __syncthreads();

    const int warp = tid >> 5, lane = tid & 31;
    const int g = lane >> 2, t = lane & 3;
    const int wr = warp << 4;
    const int row = tid >> 1, half = tid & 1;

    int nTiles = (n_nodes + 127) >> 7;

    for (int tile = blockIdx.x; tile < nTiles; tile += gridDim.x) {
        int nbase = tile << 7;

        {
            int nr = nbase + row;
            int nid = nr < n_nodes ? nr : (n_nodes - 1);
            const float4* src;
            float scale;
            if (half == 0) {
                src = (const float4*)(feats + (size_t)nid * 64);
                scale = 1.0f;
            } else {
                src = (const float4*)(g_agg + (size_t)nid * 64);
                scale = 1.0f / fmaxf(g_deg[nid], 1.0f);
            }
            #pragma unroll
            for (int cc = 0; cc < 8; cc++) {
                float4 va = src[cc * 2], vb = src[cc * 2 + 1];
                va.x *= scale; va.y *= scale; va.z *= scale; va.w *= scale;
                vb.x *= scale; vb.y *= scale; vb.z *= scale; vb.w *= scale;
                uint4 uh, ul;
                split2(va.x, va.y, uh.x, ul.x);
                split2(va.z, va.w, uh.y, ul.y);
                split2(vb.x, vb.y, uh.z, ul.z);
                split2(vb.z, vb.w, uh.w, ul.w);
                int col = half * 64 + cc * 8;
                int widx = row * 68 + (col >> 1);
                *(uint4*)(sA_hi + widx) = uh;
                *(uint4*)(sA_lo + widx) = ul;
            }
        }
        __syncwarp();

        float d[8][4];
        #pragma unroll
        for (int i = 0; i < 8; i++)
            #pragma unroll
            for (int j = 0; j < 4; j++) d[i][j] = 0.0f;

        #pragma unroll 1
        for (int kt = 0; kt < 8; kt++) {
            int ab = (wr + g) * 68 + kt * 8 + t;
            uint32_t ah[4], al[4];
            ah[0] = sA_hi[ab];       ah[1] = sA_hi[ab + 544];
            ah[2] = sA_hi[ab + 4];   ah[3] = sA_hi[ab + 548];
            al[0] = sA_lo[ab];       al[1] = sA_lo[ab + 544];
            al[2] = sA_lo[ab + 4];   al[3] = sA_lo[ab + 548];
            #pragma unroll
            for (int nt = 0; nt < 8; nt++) {
                int bb = (nt * 8 + g) * 68 + kt * 8 + t;
                uint32_t bh[2] = { sW1_hi[bb], sW1_hi[bb + 4] };
                uint32_t bl[2] = { sW1_lo[bb], sW1_lo[bb + 4] };
                mma16816(d[nt], ah, bh);
                mma16816(d[nt], ah, bl);
                mma16816(d[nt], al, bh);
            }
        }

        #pragma unroll
        for (int nt = 0; nt < 8; nt++) {
            int c0 = nt * 8 + 2 * t;
            float bb0 = bias1[c0], bb1 = bias1[c0 + 1];
            float h0 = fmaxf(d[nt][0] + bb0, 0.f), h1 = fmaxf(d[nt][1] + bb1, 0.f);
            float h2 = fmaxf(d[nt][2] + bb0, 0.f), h3 = fmaxf(d[nt][3] + bb1, 0.f);
            uint32_t uh, ul;
            int w0 = (wr + g) * 36 + nt * 4 + t;
            split2(h0, h1, uh, ul);
            sH_hi[w0] = uh; sH_lo[w0] = ul;
            split2(h2, h3, uh, ul);
            sH_hi[w0 + 288] = uh; sH_lo[w0 + 288] = ul;
        }
        __syncwarp();

        float d2[8][4];
        #pragma unroll
        for (int i = 0; i < 8; i++)
            #pragma unroll
            for (int j = 0; j < 4; j++) d2[i][j] = 0.0f;

        #pragma unroll 1
        for (int kt = 0; kt < 4; kt++) {
            int ab = (wr + g) * 36 + kt * 8 + t;
            uint32_t ah[4], al[4];
            ah[0] = sH_hi[ab];       ah[1] = sH_hi[ab + 288];
            ah[2] = sH_hi[ab + 4];   ah[3] = sH_hi[ab + 292];
            al[0] = sH_lo[ab];       al[1] = sH_lo[ab + 288];
            al[2] = sH_lo[ab + 4];   al[3] = sH_lo[ab + 292];
            #pragma unroll
            for (int nt = 0; nt < 8; nt++) {
                int bb = (nt * 8 + g) * 36 + kt * 8 + t;
                uint32_t bh[2] = { sW2_hi[bb], sW2_hi[bb + 4] };
                uint32_t bl[2] = { sW2_lo[bb], sW2_lo[bb + 4] };
                mma16816(d2[nt], ah, bh);
                mma16816(d2[nt], ah, bl);
                mma16816(d2[nt], al, bh);
            }
        }

        {
            int r0 = nbase + wr + g, r1 = r0 + 8;
            bool v0 = r0 < n_nodes, v1 = r1 < n_nodes;
            #pragma unroll
            for (int nt = 0; nt < 8; nt++) {
                int c0 = nt * 8 + 2 * t;
                float bb0 = bias2[c0], bb1 = bias2[c0 + 1];
                if (v0)
                    *(float2*)(feats_out + (size_t)r0 * 64 + c0) =
                        make_float2(d2[nt][0] + bb0, d2[nt][1] + bb1);
                if (v1)
                    *(float2*)(feats_out + (size_t)r1 * 64 + c0) =
                        make_float2(d2[nt][2] + bb0, d2[nt][3] + bb1);
            }
        }
        __syncwarp();
    }
}

// ======================= launch =======================
extern "C" void kernel_launch(void* const* d_in, const int* in_sizes, int n_in,
                              void* d_out, int out_size) {
    const float* feats      = (const float*)d_in[0];
    const int*   edge_index = (const int*)d_in[1];
    const float* edge_attr  = (const float*)d_in[2];
    const float* W1e        = (const float*)d_in[3];
    const float* b1e        = (const float*)d_in[4];
    const float* W2e        = (const float*)d_in[5];
    const float* b2e        = (const float*)d_in[6];
    const float* W1n        = (const float*)d_in[7];
    const float* b1n        = (const float*)d_in[8];
    const float* W2n        = (const float*)d_in[9];
    const float* b2n        = (const float*)d_in[10];

    int n_nodes = in_sizes[0] / 64;
    int n_edges = in_sizes[2] / 64;

    float* out       = (float*)d_out;
    float* feats_out = out;                          // [n_nodes, 64]
    float* e_out     = out + (size_t)n_nodes * 64;   // [n_edges, 64]

    cudaFuncSetAttribute(pnode_kernel, cudaFuncAttributeMaxDynamicSharedMemorySize, P_SMEM);
    cudaFuncSetAttribute(edge_kernel, cudaFuncAttributeMaxDynamicSharedMemorySize, E_SMEM);
    cudaFuncSetAttribute(node_kernel, cudaFuncAttributeMaxDynamicSharedMemorySize, N_SMEM);

    zero_kernel<<<1024, 256>>>(n_nodes);
    pnode_kernel<<<296, 256, P_SMEM>>>(feats, W1e, n_nodes);
    edge_kernel<<<296, 256, E_SMEM>>>(feats, edge_index, edge_attr,
                                      W1e, b1e, W2e, b2e, e_out, n_edges);
    node_kernel<<<148, 256, N_SMEM>>>(feats, W1n, b1n, W2n, b2n,
                                      feats_out, n_nodes);
}